// round 1
// baseline (speedup 1.0000x reference)
#include <cuda_runtime.h>

#define Vv 50257
#define Hd 1024
#define Sd 2048
#define TWO_H 2048
#define VS (Vv + Sd)          // 52305
#define POS_H1 VS             // h1 at out[52305..53329)
#define POS_C1 (VS + Hd)      // c1 at out[53329..54353)

// ---------------- scratch (no allocation allowed) ----------------
__device__ float g_att[Sd];
__device__ float g_attnw[Sd];
__device__ float g_rho[Sd];
__device__ float g_ctx[TWO_H];
__device__ float g_sel0[TWO_H];
__device__ float g_lstm_in[3 * Hd];
__device__ float g_h1[Hd];
__device__ float g_pmax[64];
__device__ float g_psum[64];

// ---------------- helpers ----------------
__device__ __forceinline__ float wredsum(float v) {
#pragma unroll
    for (int o = 16; o; o >>= 1) v += __shfl_xor_sync(0xffffffffu, v, o);
    return v;
}

__device__ __forceinline__ float blockSum(float v) {
    __shared__ float red[32];
    int lane = threadIdx.x & 31, w = threadIdx.x >> 5;
    int nw = (blockDim.x + 31) >> 5;
    v = wredsum(v);
    if (lane == 0) red[w] = v;
    __syncthreads();
    if (threadIdx.x == 0) {
        float s = 0.f;
        for (int i = 0; i < nw; i++) s += red[i];
        red[0] = s;
    }
    __syncthreads();
    float r = red[0];
    __syncthreads();
    return r;
}

__device__ __forceinline__ float blockMax(float v) {
    __shared__ float red[32];
    int lane = threadIdx.x & 31, w = threadIdx.x >> 5;
    int nw = (blockDim.x + 31) >> 5;
#pragma unroll
    for (int o = 16; o; o >>= 1) v = fmaxf(v, __shfl_xor_sync(0xffffffffu, v, o));
    if (lane == 0) red[w] = v;
    __syncthreads();
    if (threadIdx.x == 0) {
        float s = -3.4e38f;
        for (int i = 0; i < nw; i++) s = fmaxf(s, red[i]);
        red[0] = s;
    }
    __syncthreads();
    float r = red[0];
    __syncthreads();
    return r;
}

// packed f32x2 FMA (sm_103a FFMA2 — 2x fp32 FMA throughput)
__device__ __forceinline__ unsigned long long ffma2(unsigned long long a,
                                                    unsigned long long b,
                                                    unsigned long long c) {
    unsigned long long d;
    asm("fma.rn.f32x2 %0, %1, %2, %3;" : "=l"(d) : "l"(a), "l"(b), "l"(c));
    return d;
}
__device__ __forceinline__ unsigned long long pk2(float x, float y) {
    unsigned long long u;
    asm("mov.b64 %0, {%1,%2};" : "=l"(u) : "f"(x), "f"(y));
    return u;
}
__device__ __forceinline__ float2 upk2(unsigned long long u) {
    float2 f;
    asm("mov.b64 {%0,%1}, %2;" : "=f"(f.x), "=f"(f.y) : "l"(u));
    return f;
}

__device__ __forceinline__ float sigf(float x) { return 1.f / (1.f + expf(-x)); }

// ---------------- K0: zero accumulators ----------------
__global__ void k_zero(float* __restrict__ out) {
    int i = blockIdx.x * blockDim.x + threadIdx.x;
    if (i < TWO_H) { g_ctx[i] = 0.f; g_sel0[i] = 0.f; }
    if (i < Sd) out[Vv + i] = 0.f;
}

// ---------------- K1: att_logits = [xe,h] @ attn_W.T + attn_b ----------------
__global__ void k_att(const float* __restrict__ x, const float* __restrict__ h0,
                      const float* __restrict__ attn_W, const float* __restrict__ attn_b) {
    __shared__ float z[TWO_H];
    int t = threadIdx.x;
    for (int i = t; i < Hd; i += 256) { z[i] = x[i]; z[Hd + i] = h0[i]; }
    __syncthreads();
    int warp = t >> 5, lane = t & 31;
    int row = blockIdx.x * 8 + warp;
    const float4* W = (const float4*)(attn_W + (size_t)row * TWO_H);
    const float4* Z = (const float4*)z;
    float s = 0.f;
#pragma unroll 4
    for (int i = lane; i < TWO_H / 4; i += 32) {
        float4 w = W[i], zz = Z[i];
        s += w.x * zz.x + w.y * zz.y + w.z * zz.z + w.w * zz.w;
    }
    s = wredsum(s);
    if (lane == 0) g_att[row] = s + attn_b[row];
}

// ---------------- K2: softmax(att), rho, copy xe into lstm_in ----------------
__global__ void k_soft_rho(const int* __restrict__ sentence,
                           const float* __restrict__ prev_probs,
                           const int* __restrict__ prev_word,
                           const float* __restrict__ x) {
    int t = threadIdx.x;  // 1024 threads
    g_lstm_in[t] = x[t];
    float a0 = g_att[t], a1 = g_att[t + 1024];
    float M = blockMax(fmaxf(a0, a1));
    float e0 = expf(a0 - M), e1 = expf(a1 - M);
    float Ssum = blockSum(e0 + e1);
    float inv = 1.f / Ssum;
    g_attnw[t] = e0 * inv;
    g_attnw[t + 1024] = e1 * inv;

    int pw = prev_word[0];
    float r0 = (sentence[t] == pw) ? prev_probs[Vv + t] : 0.f;
    float r1 = (sentence[t + 1024] == pw) ? prev_probs[Vv + t + 1024] : 0.f;
    float Rs = blockSum(r0 + r1);
    float rin = 1.f / (Rs + 1e-9f);
    g_rho[t] = r0 * rin;
    g_rho[t + 1024] = r1 * rin;
}

// ---------------- K3: ctx = attn_w @ enc ; sel0 = rho @ enc ----------------
__global__ void k_ctx(const float* __restrict__ enc) {
    __shared__ float aw[128], rh[128];
    int t = threadIdx.x;
    int cb = blockIdx.x & 7;   // 8 column blocks of 256
    int sc = blockIdx.x >> 3;  // 16 s-chunks of 128
    int col = cb * 256 + t;
    int s0 = sc * 128;
    if (t < 128) { aw[t] = g_attnw[s0 + t]; rh[t] = g_rho[s0 + t]; }
    __syncthreads();
    float ac = 0.f, as = 0.f;
#pragma unroll 4
    for (int i = 0; i < 128; i++) {
        float e = enc[(size_t)(s0 + i) * TWO_H + col];
        ac += aw[i] * e;
        as += rh[i] * e;
    }
    atomicAdd(&g_ctx[col], ac);
    atomicAdd(&g_sel0[col], as);
}

// ---------------- K4: attentive / selective projections ----------------
__global__ void k_proj(const float* __restrict__ comb_W, const float* __restrict__ comb_b,
                       const float* __restrict__ Ws_W, const float* __restrict__ Ws_b) {
    __shared__ float v[TWO_H];
    int t = threadIdx.x;
    bool sel = blockIdx.x < 128;
    const float* src = sel ? g_sel0 : g_ctx;
    for (int i = t; i < TWO_H; i += 256) v[i] = src[i];
    __syncthreads();
    int warp = t >> 5, lane = t & 31;
    int row = (blockIdx.x & 127) * 8 + warp;  // 0..1023
    const float* W = sel ? Ws_W : comb_W;
    const float4* Wr = (const float4*)(W + (size_t)row * TWO_H);
    const float4* Zv = (const float4*)v;
    float s = 0.f;
#pragma unroll 4
    for (int i = lane; i < TWO_H / 4; i += 32) {
        float4 w = Wr[i], z = Zv[i];
        s += w.x * z.x + w.y * z.y + w.z * z.z + w.w * z.w;
    }
    s = wredsum(s);
    if (lane == 0) {
        if (sel) g_lstm_in[Hd + row] = s + Ws_b[row];
        else     g_lstm_in[2 * Hd + row] = s + comb_b[row];
    }
}

// ---------------- K5: gates + LSTM cell (warp k does rows k,k+H,k+2H,k+3H) --------
__global__ void k_lstm(const float* __restrict__ W_ih, const float* __restrict__ W_hh,
                       const float* __restrict__ b_ih, const float* __restrict__ b_hh,
                       const float* __restrict__ h0, const float* __restrict__ c0,
                       float* __restrict__ out) {
    __shared__ float lin[3 * Hd];
    __shared__ float hh[Hd];
    int t = threadIdx.x;
    for (int i = t; i < 3 * Hd; i += 256) lin[i] = g_lstm_in[i];
    for (int i = t; i < Hd; i += 256) hh[i] = h0[i];
    __syncthreads();
    int warp = t >> 5, lane = t & 31;
    int k = blockIdx.x * 8 + warp;
    float acc[4];
#pragma unroll
    for (int r = 0; r < 4; r++) {
        int row = k + r * Hd;
        const float4* Wi = (const float4*)(W_ih + (size_t)row * (3 * Hd));
        const float4* Wh = (const float4*)(W_hh + (size_t)row * Hd);
        const float4* L = (const float4*)lin;
        const float4* Hf = (const float4*)hh;
        float s = 0.f;
#pragma unroll 4
        for (int i = lane; i < 3 * Hd / 4; i += 32) {
            float4 w = Wi[i], z = L[i];
            s += w.x * z.x + w.y * z.y + w.z * z.z + w.w * z.w;
        }
#pragma unroll 4
        for (int i = lane; i < Hd / 4; i += 32) {
            float4 w = Wh[i], z = Hf[i];
            s += w.x * z.x + w.y * z.y + w.z * z.z + w.w * z.w;
        }
        acc[r] = s;
    }
#pragma unroll
    for (int r = 0; r < 4; r++) acc[r] = wredsum(acc[r]);
    if (lane == 0) {
        float iv = acc[0] + b_ih[k] + b_hh[k];
        float fv = acc[1] + b_ih[k + Hd] + b_hh[k + Hd];
        float gv = acc[2] + b_ih[k + 2 * Hd] + b_hh[k + 2 * Hd];
        float ov = acc[3] + b_ih[k + 3 * Hd] + b_hh[k + 3 * Hd];
        float c1 = sigf(fv) * c0[k] + sigf(iv) * tanhf(gv);
        float h1 = sigf(ov) * tanhf(c1);
        g_h1[k] = h1;
        out[POS_H1 + k] = h1;
        out[POS_C1 + k] = c1;
    }
}

// ---------------- K6: score_g = h1 @ Wo_W.T + Wo_b (206 MB, BW-bound) -----------
__global__ void k_scoreg(const float* __restrict__ Wo_W, const float* __restrict__ Wo_b,
                         float* __restrict__ out) {
    __shared__ float h[Hd];
    int t = threadIdx.x;
    for (int i = t; i < Hd; i += 256) h[i] = g_h1[i];
    __syncthreads();
    int warp = t >> 5, lane = t & 31;
    int row = blockIdx.x * 8 + warp;
    if (row >= Vv) return;
    const float4* W = (const float4*)(Wo_W + (size_t)row * Hd);
    const float4* Hf = (const float4*)h;
    float s = 0.f;
#pragma unroll 4
    for (int i = lane; i < Hd / 4; i += 32) {
        float4 w = W[i], z = Hf[i];
        s += w.x * z.x + w.y * z.y + w.z * z.z + w.w * z.w;
    }
    s = wredsum(s);
    if (lane == 0) out[row] = s + Wo_b[row];
}

// ---------------- K7: score_c = tanh(enc @ Wc_W.T + b) @ h1 (FFMA2 SGEMM) -------
__global__ void k_scorec(const float* __restrict__ enc, const float* __restrict__ Wc_W,
                         const float* __restrict__ Wc_b, float* __restrict__ out) {
    __shared__ float As[32][68];
    __shared__ float Bs[32][68];
    __shared__ float hs[64], bs[64], srow[64];
    int t = threadIdx.x;           // 256
    int tx = t & 15, ty = t >> 4;  // 16x16
    int s0 = blockIdx.x * 64, j0 = blockIdx.y * 64;
    if (t < 64) { hs[t] = g_h1[j0 + t]; bs[t] = Wc_b[j0 + t]; srow[t] = 0.f; }

    unsigned long long c[4][2] = {};
    for (int k0 = 0; k0 < TWO_H; k0 += 32) {
        __syncthreads();
#pragma unroll
        for (int l = t; l < 2048; l += 256) {
            int row = l >> 5, kk = l & 31;
            As[kk][row] = enc[(size_t)(s0 + row) * TWO_H + k0 + kk];
            Bs[kk][row] = Wc_W[(size_t)(j0 + row) * TWO_H + k0 + kk];
        }
        __syncthreads();
#pragma unroll
        for (int kk = 0; kk < 32; kk++) {
            float4 av = *(const float4*)&As[kk][ty * 4];
            ulonglong2 bv = *(const ulonglong2*)&Bs[kk][tx * 4];
            unsigned long long a0 = pk2(av.x, av.x), a1 = pk2(av.y, av.y);
            unsigned long long a2 = pk2(av.z, av.z), a3 = pk2(av.w, av.w);
            c[0][0] = ffma2(a0, bv.x, c[0][0]); c[0][1] = ffma2(a0, bv.y, c[0][1]);
            c[1][0] = ffma2(a1, bv.x, c[1][0]); c[1][1] = ffma2(a1, bv.y, c[1][1]);
            c[2][0] = ffma2(a2, bv.x, c[2][0]); c[2][1] = ffma2(a2, bv.y, c[2][1]);
            c[3][0] = ffma2(a3, bv.x, c[3][0]); c[3][1] = ffma2(a3, bv.y, c[3][1]);
        }
    }
    __syncthreads();
#pragma unroll
    for (int i = 0; i < 4; i++) {
        float part = 0.f;
#pragma unroll
        for (int j = 0; j < 2; j++) {
            float2 f = upk2(c[i][j]);
            int jj = tx * 4 + j * 2;
            part += tanhf(f.x + bs[jj]) * hs[jj];
            part += tanhf(f.y + bs[jj + 1]) * hs[jj + 1];
        }
        atomicAdd(&srow[ty * 4 + i], part);
    }
    __syncthreads();
    if (t < 64) atomicAdd(&out[Vv + s0 + t], srow[t]);
}

// ---------------- final softmax over out[0:VS) (3 kernels) ----------------
__global__ void k_pmax(const float* __restrict__ out) {
    float m = -3.4e38f;
    for (int i = blockIdx.x * 256 + threadIdx.x; i < VS; i += 64 * 256)
        m = fmaxf(m, out[i]);
    m = blockMax(m);
    if (threadIdx.x == 0) g_pmax[blockIdx.x] = m;
}

__global__ void k_expsum(float* __restrict__ out) {
    float m = -3.4e38f;
    for (int i = threadIdx.x; i < 64; i += 256) m = fmaxf(m, g_pmax[i]);
    float M = blockMax(m);
    float s = 0.f;
    for (int i = blockIdx.x * 256 + threadIdx.x; i < VS; i += 64 * 256) {
        float e = expf(out[i] - M);
        out[i] = e;
        s += e;
    }
    s = blockSum(s);
    if (threadIdx.x == 0) g_psum[blockIdx.x] = s;
}

__global__ void k_norm(float* __restrict__ out) {
    float s = 0.f;
    for (int i = threadIdx.x; i < 64; i += 256) s += g_psum[i];
    float tot = blockSum(s);
    float inv = 1.f / tot;
    for (int i = blockIdx.x * 256 + threadIdx.x; i < VS; i += 64 * 256)
        out[i] *= inv;
}

// ---------------- launch ----------------
extern "C" void kernel_launch(void* const* d_in, const int* in_sizes, int n_in,
                              void* d_out, int out_size) {
    const float* x          = (const float*)d_in[0];
    const float* enc        = (const float*)d_in[1];
    const int*   sentence   = (const int*)d_in[2];
    const float* prev_probs = (const float*)d_in[3];
    const float* h0         = (const float*)d_in[4];
    const float* c0         = (const float*)d_in[5];
    const float* attn_W     = (const float*)d_in[6];
    const float* attn_b     = (const float*)d_in[7];
    const float* comb_W     = (const float*)d_in[8];
    const float* comb_b     = (const float*)d_in[9];
    const float* Ws_W       = (const float*)d_in[10];
    const float* Ws_b       = (const float*)d_in[11];
    const float* Wo_W       = (const float*)d_in[12];
    const float* Wo_b       = (const float*)d_in[13];
    const float* Wc_W       = (const float*)d_in[14];
    const float* Wc_b       = (const float*)d_in[15];
    const float* W_ih       = (const float*)d_in[16];
    const float* W_hh       = (const float*)d_in[17];
    const float* b_ih       = (const float*)d_in[18];
    const float* b_hh       = (const float*)d_in[19];
    const int*   prev_word  = (const int*)d_in[20];
    float* out = (float*)d_out;

    k_zero<<<8, 256>>>(out);
    k_att<<<256, 256>>>(x, h0, attn_W, attn_b);
    k_soft_rho<<<1, 1024>>>(sentence, prev_probs, prev_word, x);
    k_ctx<<<128, 256>>>(enc);
    k_proj<<<256, 256>>>(comb_W, comb_b, Ws_W, Ws_b);
    k_lstm<<<128, 256>>>(W_ih, W_hh, b_ih, b_hh, h0, c0, out);
    k_scoreg<<<6283, 256>>>(Wo_W, Wo_b, out);
    dim3 g7(Sd / 64, Hd / 64);
    k_scorec<<<g7, 256>>>(enc, Wc_W, Wc_b, out);
    k_pmax<<<64, 256>>>(out);
    k_expsum<<<64, 256>>>(out);
    k_norm<<<64, 256>>>(out);
}

// round 2
// speedup vs baseline: 2.0654x; 2.0654x over previous
#include <cuda_runtime.h>

#define Vv 50257
#define Hd 1024
#define Sd 2048
#define TWO_H 2048
#define VS (Vv + Sd)          // 52305
#define POS_H1 VS
#define POS_C1 (VS + Hd)

// ---------------- scratch ----------------
__device__ float g_att[Sd];
__device__ float g_attnw[Sd];
__device__ float g_rho[Sd];
__device__ float g_ctx[TWO_H];
__device__ float g_sel0[TWO_H];
__device__ float g_lstm_in[3 * Hd];
__device__ float g_gates[4 * Hd];
__device__ float g_h1[Hd];
__device__ float g_pmax[64];
__device__ float g_psum[64];

// ---------------- helpers ----------------
__device__ __forceinline__ float wredsum(float v) {
#pragma unroll
    for (int o = 16; o; o >>= 1) v += __shfl_xor_sync(0xffffffffu, v, o);
    return v;
}

__device__ __forceinline__ float blockSum(float v) {
    __shared__ float red[32];
    int lane = threadIdx.x & 31, w = threadIdx.x >> 5;
    int nw = (blockDim.x + 31) >> 5;
    v = wredsum(v);
    if (lane == 0) red[w] = v;
    __syncthreads();
    if (threadIdx.x == 0) {
        float s = 0.f;
        for (int i = 0; i < nw; i++) s += red[i];
        red[0] = s;
    }
    __syncthreads();
    float r = red[0];
    __syncthreads();
    return r;
}

__device__ __forceinline__ float blockMax(float v) {
    __shared__ float red[32];
    int lane = threadIdx.x & 31, w = threadIdx.x >> 5;
    int nw = (blockDim.x + 31) >> 5;
#pragma unroll
    for (int o = 16; o; o >>= 1) v = fmaxf(v, __shfl_xor_sync(0xffffffffu, v, o));
    if (lane == 0) red[w] = v;
    __syncthreads();
    if (threadIdx.x == 0) {
        float s = -3.4e38f;
        for (int i = 0; i < nw; i++) s = fmaxf(s, red[i]);
        red[0] = s;
    }
    __syncthreads();
    float r = red[0];
    __syncthreads();
    return r;
}

__device__ __forceinline__ unsigned long long ffma2(unsigned long long a,
                                                    unsigned long long b,
                                                    unsigned long long c) {
    unsigned long long d;
    asm("fma.rn.f32x2 %0, %1, %2, %3;" : "=l"(d) : "l"(a), "l"(b), "l"(c));
    return d;
}
__device__ __forceinline__ unsigned long long pk2(float x, float y) {
    unsigned long long u;
    asm("mov.b64 %0, {%1,%2};" : "=l"(u) : "f"(x), "f"(y));
    return u;
}
__device__ __forceinline__ float2 upk2(unsigned long long u) {
    float2 f;
    asm("mov.b64 {%0,%1}, %2;" : "=f"(f.x), "=f"(f.y) : "l"(u));
    return f;
}
__device__ __forceinline__ float dot4(float4 a, float4 b) {
    return a.x * b.x + a.y * b.y + a.z * b.z + a.w * b.w;
}
__device__ __forceinline__ float sigf(float x) { return 1.f / (1.f + expf(-x)); }

// ---------------- K0: zero accumulators ----------------
__global__ void k_zero(float* __restrict__ out) {
    int i = blockIdx.x * blockDim.x + threadIdx.x;
    if (i < TWO_H) { g_ctx[i] = 0.f; g_sel0[i] = 0.f; }
    if (i < Sd) out[Vv + i] = 0.f;
}

// ---------------- K1: att_logits = [xe,h] @ attn_W.T + attn_b ----------------
// 2 rows per warp, 16 unrolled loads in flight.
__global__ void k_att(const float* __restrict__ x, const float* __restrict__ h0,
                      const float* __restrict__ attn_W, const float* __restrict__ attn_b) {
    __shared__ float z[TWO_H];
    int t = threadIdx.x, lane = t & 31, warp = t >> 5;
    for (int i = t; i < Hd; i += 256) { z[i] = x[i]; z[Hd + i] = h0[i]; }
    __syncthreads();
    int r0 = blockIdx.x * 16 + warp * 2, r1 = r0 + 1;
    const float4* W0 = (const float4*)(attn_W + (size_t)r0 * TWO_H);
    const float4* W1 = (const float4*)(attn_W + (size_t)r1 * TWO_H);
    const float4* Z = (const float4*)z;
    float s0 = 0.f, s1 = 0.f;
#pragma unroll
    for (int half = 0; half < 2; half++) {
        float4 a[8], b[8];
#pragma unroll
        for (int j = 0; j < 8; j++) a[j] = W0[lane + (half * 8 + j) * 32];
#pragma unroll
        for (int j = 0; j < 8; j++) b[j] = W1[lane + (half * 8 + j) * 32];
#pragma unroll
        for (int j = 0; j < 8; j++) {
            float4 zz = Z[lane + (half * 8 + j) * 32];
            s0 += dot4(a[j], zz);
            s1 += dot4(b[j], zz);
        }
    }
    s0 = wredsum(s0);
    s1 = wredsum(s1);
    if (lane == 0) {
        g_att[r0] = s0 + attn_b[r0];
        g_att[r1] = s1 + attn_b[r1];
    }
}

// ---------------- K2: softmax(att), rho, copy xe ----------------
__global__ void k_soft_rho(const int* __restrict__ sentence,
                           const float* __restrict__ prev_probs,
                           const int* __restrict__ prev_word,
                           const float* __restrict__ x) {
    int t = threadIdx.x;  // 1024
    g_lstm_in[t] = x[t];
    float a0 = g_att[t], a1 = g_att[t + 1024];
    float M = blockMax(fmaxf(a0, a1));
    float e0 = expf(a0 - M), e1 = expf(a1 - M);
    float Ssum = blockSum(e0 + e1);
    float inv = 1.f / Ssum;
    g_attnw[t] = e0 * inv;
    g_attnw[t + 1024] = e1 * inv;

    int pw = prev_word[0];
    float r0 = (sentence[t] == pw) ? prev_probs[Vv + t] : 0.f;
    float r1 = (sentence[t + 1024] == pw) ? prev_probs[Vv + t + 1024] : 0.f;
    float Rs = blockSum(r0 + r1);
    float rin = 1.f / (Rs + 1e-9f);
    g_rho[t] = r0 * rin;
    g_rho[t + 1024] = r1 * rin;
}

// ---------------- K3: ctx = attn_w @ enc ; sel0 = rho @ enc ----------------
__global__ void k_ctx(const float* __restrict__ enc) {
    __shared__ float aw[64], rh[64];
    int t = threadIdx.x;
    int cb = blockIdx.x & 7;    // 8 col chunks of 256
    int sc = blockIdx.x >> 3;   // 32 s chunks of 64
    int col = cb * 256 + t;
    int s0 = sc * 64;
    if (t < 64) { aw[t] = g_attnw[s0 + t]; rh[t] = g_rho[s0 + t]; }
    __syncthreads();
    float ac = 0.f, as = 0.f;
#pragma unroll 8
    for (int i = 0; i < 64; i++) {
        float e = enc[(size_t)(s0 + i) * TWO_H + col];
        ac += aw[i] * e;
        as += rh[i] * e;
    }
    atomicAdd(&g_ctx[col], ac);
    atomicAdd(&g_sel0[col], as);
}

// ---------------- K4: attentive / selective projections ----------------
// virtual rows 0..2047: [0,1024) = Ws(sel0), [1024,2048) = comb(ctx)
__global__ void k_proj(const float* __restrict__ comb_W, const float* __restrict__ comb_b,
                       const float* __restrict__ Ws_W, const float* __restrict__ Ws_b) {
    __shared__ float z[TWO_H];
    int t = threadIdx.x, lane = t & 31, warp = t >> 5;
    bool sel = blockIdx.x < 64;
    const float* src = sel ? g_sel0 : g_ctx;
    for (int i = t; i < TWO_H; i += 256) z[i] = src[i];
    __syncthreads();
    int r0 = (blockIdx.x & 63) * 16 + warp * 2, r1 = r0 + 1;  // 0..1023
    const float* W = sel ? Ws_W : comb_W;
    const float4* W0 = (const float4*)(W + (size_t)r0 * TWO_H);
    const float4* W1 = (const float4*)(W + (size_t)r1 * TWO_H);
    const float4* Z = (const float4*)z;
    float s0 = 0.f, s1 = 0.f;
#pragma unroll
    for (int half = 0; half < 2; half++) {
        float4 a[8], b[8];
#pragma unroll
        for (int j = 0; j < 8; j++) a[j] = W0[lane + (half * 8 + j) * 32];
#pragma unroll
        for (int j = 0; j < 8; j++) b[j] = W1[lane + (half * 8 + j) * 32];
#pragma unroll
        for (int j = 0; j < 8; j++) {
            float4 zz = Z[lane + (half * 8 + j) * 32];
            s0 += dot4(a[j], zz);
            s1 += dot4(b[j], zz);
        }
    }
    s0 = wredsum(s0);
    s1 = wredsum(s1);
    if (lane == 0) {
        if (sel) { g_lstm_in[Hd + r0] = s0 + Ws_b[r0]; g_lstm_in[Hd + r1] = s1 + Ws_b[r1]; }
        else     { g_lstm_in[2 * Hd + r0] = s0 + comb_b[r0]; g_lstm_in[2 * Hd + r1] = s1 + comb_b[r1]; }
    }
}

// ---------------- K5a: gates GEMV (4096 rows over [lin(3072), h0(1024)]) -------
__global__ void k_gates(const float* __restrict__ W_ih, const float* __restrict__ W_hh,
                        const float* __restrict__ h0) {
    __shared__ float zin[4096];
    int t = threadIdx.x, lane = t & 31, warp = t >> 5;
    for (int i = t; i < 3 * Hd; i += 256) zin[i] = g_lstm_in[i];
    for (int i = t; i < Hd; i += 256) zin[3 * Hd + i] = h0[i];
    __syncthreads();
    int r0 = blockIdx.x * 16 + warp * 2, r1 = r0 + 1;  // 0..4095
    const float4* Wi0 = (const float4*)(W_ih + (size_t)r0 * (3 * Hd));
    const float4* Wi1 = (const float4*)(W_ih + (size_t)r1 * (3 * Hd));
    const float4* Wh0 = (const float4*)(W_hh + (size_t)r0 * Hd);
    const float4* Wh1 = (const float4*)(W_hh + (size_t)r1 * Hd);
    const float4* Z = (const float4*)zin;
    float s0 = 0.f, s1 = 0.f;
#pragma unroll
    for (int bch = 0; bch < 3; bch++) {  // W_ih part: float4 idx 0..767
        float4 a[8], b[8];
#pragma unroll
        for (int j = 0; j < 8; j++) a[j] = Wi0[lane + (bch * 8 + j) * 32];
#pragma unroll
        for (int j = 0; j < 8; j++) b[j] = Wi1[lane + (bch * 8 + j) * 32];
#pragma unroll
        for (int j = 0; j < 8; j++) {
            float4 zz = Z[lane + (bch * 8 + j) * 32];
            s0 += dot4(a[j], zz);
            s1 += dot4(b[j], zz);
        }
    }
    {   // W_hh part vs zin[3072..)
        float4 a[8], b[8];
#pragma unroll
        for (int j = 0; j < 8; j++) a[j] = Wh0[lane + j * 32];
#pragma unroll
        for (int j = 0; j < 8; j++) b[j] = Wh1[lane + j * 32];
#pragma unroll
        for (int j = 0; j < 8; j++) {
            float4 zz = Z[768 + lane + j * 32];
            s0 += dot4(a[j], zz);
            s1 += dot4(b[j], zz);
        }
    }
    s0 = wredsum(s0);
    s1 = wredsum(s1);
    if (lane == 0) { g_gates[r0] = s0; g_gates[r1] = s1; }
}

// ---------------- K5b: LSTM cell pointwise ----------------
__global__ void k_cell(const float* __restrict__ b_ih, const float* __restrict__ b_hh,
                       const float* __restrict__ c0, float* __restrict__ out) {
    int k = blockIdx.x * 256 + threadIdx.x;  // 0..1023
    float iv = g_gates[k]          + b_ih[k]          + b_hh[k];
    float fv = g_gates[k + Hd]     + b_ih[k + Hd]     + b_hh[k + Hd];
    float gv = g_gates[k + 2 * Hd] + b_ih[k + 2 * Hd] + b_hh[k + 2 * Hd];
    float ov = g_gates[k + 3 * Hd] + b_ih[k + 3 * Hd] + b_hh[k + 3 * Hd];
    float c1 = sigf(fv) * c0[k] + sigf(iv) * tanhf(gv);
    float h1 = sigf(ov) * tanhf(c1);
    g_h1[k] = h1;
    out[POS_H1 + k] = h1;
    out[POS_C1 + k] = c1;
}

// ---------------- K6: score_g = h1 @ Wo_W.T + Wo_b (206 MB) ----------------
// 2 rows/warp, h in registers, 16 LDG.128 in flight, no smem/sync.
__global__ void k_scoreg(const float* __restrict__ Wo_W, const float* __restrict__ Wo_b,
                         float* __restrict__ out) {
    int t = threadIdx.x, lane = t & 31;
    int warpg = blockIdx.x * 8 + (t >> 5);
    int r0 = warpg * 2, r1 = r0 + 1;
    if (r0 >= Vv) return;
    float4 hf[8];
    const float4* H4 = (const float4*)g_h1;
#pragma unroll
    for (int j = 0; j < 8; j++) hf[j] = H4[lane + j * 32];
    const float4* W0 = (const float4*)(Wo_W + (size_t)r0 * Hd);
    const float4* W1 = (const float4*)(Wo_W + (size_t)r1 * Hd);
    bool has1 = (r1 < Vv);
    float4 a[8], b[8];
#pragma unroll
    for (int j = 0; j < 8; j++) a[j] = W0[lane + j * 32];
    if (has1) {
#pragma unroll
        for (int j = 0; j < 8; j++) b[j] = W1[lane + j * 32];
    }
    float s0 = 0.f, s1 = 0.f;
#pragma unroll
    for (int j = 0; j < 8; j++) s0 += dot4(a[j], hf[j]);
    if (has1) {
#pragma unroll
        for (int j = 0; j < 8; j++) s1 += dot4(b[j], hf[j]);
    }
    s0 = wredsum(s0);
    s1 = wredsum(s1);
    if (lane == 0) {
        out[r0] = s0 + Wo_b[r0];
        if (has1) out[r1] = s1 + Wo_b[r1];
    }
}

// ---------------- K7: score_c = tanh(enc @ Wc_W.T + b) @ h1 (FFMA2) ----------
// 128x64 block tile, 256 threads, 8x4 outputs/thread (f32x2 pairs).
__global__ void k_scorec(const float* __restrict__ enc, const float* __restrict__ Wc_W,
                         const float* __restrict__ Wc_b, float* __restrict__ out) {
    __shared__ float As[32][132];
    __shared__ float Bs[32][68];
    __shared__ float hs[64], bs[64], srow[128];
    int t = threadIdx.x;
    int tx = t & 15, ty = t >> 4;
    int s0 = blockIdx.x * 128, j0 = blockIdx.y * 64;
    if (t < 64) { hs[t] = g_h1[j0 + t]; bs[t] = Wc_b[j0 + t]; }
    if (t < 128) srow[t] = 0.f;
    int m0 = ty * 8, jj0 = tx * 4;

    unsigned long long c[8][2] = {};
    for (int k0 = 0; k0 < TWO_H; k0 += 32) {
        __syncthreads();
#pragma unroll
        for (int p = 0; p < 4; p++) {  // As: 128 rows x 32 k
            int idx = t + p * 256;     // 0..1023 float4s
            int row = idx >> 3, kq = idx & 7;
            float4 v = *(const float4*)(enc + (size_t)(s0 + row) * TWO_H + k0 + kq * 4);
            As[kq * 4 + 0][row] = v.x; As[kq * 4 + 1][row] = v.y;
            As[kq * 4 + 2][row] = v.z; As[kq * 4 + 3][row] = v.w;
        }
#pragma unroll
        for (int p = 0; p < 2; p++) {  // Bs: 64 rows x 32 k
            int idx = t + p * 256;     // 0..511 float4s
            int row = idx >> 3, kq = idx & 7;
            float4 v = *(const float4*)(Wc_W + (size_t)(j0 + row) * TWO_H + k0 + kq * 4);
            Bs[kq * 4 + 0][row] = v.x; Bs[kq * 4 + 1][row] = v.y;
            Bs[kq * 4 + 2][row] = v.z; Bs[kq * 4 + 3][row] = v.w;
        }
        __syncthreads();
#pragma unroll
        for (int kk = 0; kk < 32; kk++) {
            float4 aA = *(const float4*)&As[kk][m0];
            float4 aB = *(const float4*)&As[kk][m0 + 4];
            ulonglong2 bv = *(const ulonglong2*)&Bs[kk][jj0];
            unsigned long long a0 = pk2(aA.x, aA.x), a1 = pk2(aA.y, aA.y);
            unsigned long long a2 = pk2(aA.z, aA.z), a3 = pk2(aA.w, aA.w);
            unsigned long long a4 = pk2(aB.x, aB.x), a5 = pk2(aB.y, aB.y);
            unsigned long long a6 = pk2(aB.z, aB.z), a7 = pk2(aB.w, aB.w);
            c[0][0] = ffma2(a0, bv.x, c[0][0]); c[0][1] = ffma2(a0, bv.y, c[0][1]);
            c[1][0] = ffma2(a1, bv.x, c[1][0]); c[1][1] = ffma2(a1, bv.y, c[1][1]);
            c[2][0] = ffma2(a2, bv.x, c[2][0]); c[2][1] = ffma2(a2, bv.y, c[2][1]);
            c[3][0] = ffma2(a3, bv.x, c[3][0]); c[3][1] = ffma2(a3, bv.y, c[3][1]);
            c[4][0] = ffma2(a4, bv.x, c[4][0]); c[4][1] = ffma2(a4, bv.y, c[4][1]);
            c[5][0] = ffma2(a5, bv.x, c[5][0]); c[5][1] = ffma2(a5, bv.y, c[5][1]);
            c[6][0] = ffma2(a6, bv.x, c[6][0]); c[6][1] = ffma2(a6, bv.y, c[6][1]);
            c[7][0] = ffma2(a7, bv.x, c[7][0]); c[7][1] = ffma2(a7, bv.y, c[7][1]);
        }
    }
    __syncthreads();
#pragma unroll
    for (int m = 0; m < 8; m++) {
        float part = 0.f;
#pragma unroll
        for (int jp = 0; jp < 2; jp++) {
            float2 f = upk2(c[m][jp]);
            int j = jj0 + jp * 2;
            part += tanhf(f.x + bs[j]) * hs[j];
            part += tanhf(f.y + bs[j + 1]) * hs[j + 1];
        }
        atomicAdd(&srow[m0 + m], part);
    }
    __syncthreads();
    if (t < 128) atomicAdd(&out[Vv + s0 + t], srow[t]);
}

// ---------------- final softmax over out[0:VS) ----------------
__global__ void k_pmax(const float* __restrict__ out) {
    float m = -3.4e38f;
    for (int i = blockIdx.x * 256 + threadIdx.x; i < VS; i += 64 * 256)
        m = fmaxf(m, out[i]);
    m = blockMax(m);
    if (threadIdx.x == 0) g_pmax[blockIdx.x] = m;
}

__global__ void k_expsum(float* __restrict__ out) {
    float m = -3.4e38f;
    for (int i = threadIdx.x; i < 64; i += 256) m = fmaxf(m, g_pmax[i]);
    float M = blockMax(m);
    float s = 0.f;
    for (int i = blockIdx.x * 256 + threadIdx.x; i < VS; i += 64 * 256) {
        float e = expf(out[i] - M);
        out[i] = e;
        s += e;
    }
    s = blockSum(s);
    if (threadIdx.x == 0) g_psum[blockIdx.x] = s;
}

__global__ void k_norm(float* __restrict__ out) {
    float s = 0.f;
    for (int i = threadIdx.x; i < 64; i += 256) s += g_psum[i];
    float tot = blockSum(s);
    float inv = 1.f / tot;
    for (int i = blockIdx.x * 256 + threadIdx.x; i < VS; i += 64 * 256)
        out[i] *= inv;
}

// ---------------- launch ----------------
extern "C" void kernel_launch(void* const* d_in, const int* in_sizes, int n_in,
                              void* d_out, int out_size) {
    const float* x          = (const float*)d_in[0];
    const float* enc        = (const float*)d_in[1];
    const int*   sentence   = (const int*)d_in[2];
    const float* prev_probs = (const float*)d_in[3];
    const float* h0         = (const float*)d_in[4];
    const float* c0         = (const float*)d_in[5];
    const float* attn_W     = (const float*)d_in[6];
    const float* attn_b     = (const float*)d_in[7];
    const float* comb_W     = (const float*)d_in[8];
    const float* comb_b     = (const float*)d_in[9];
    const float* Ws_W       = (const float*)d_in[10];
    const float* Ws_b       = (const float*)d_in[11];
    const float* Wo_W       = (const float*)d_in[12];
    const float* Wo_b       = (const float*)d_in[13];
    const float* Wc_W       = (const float*)d_in[14];
    const float* Wc_b       = (const float*)d_in[15];
    const float* W_ih       = (const float*)d_in[16];
    const float* W_hh       = (const float*)d_in[17];
    const float* b_ih       = (const float*)d_in[18];
    const float* b_hh       = (const float*)d_in[19];
    const int*   prev_word  = (const int*)d_in[20];
    float* out = (float*)d_out;

    k_zero<<<8, 256>>>(out);
    k_att<<<128, 256>>>(x, h0, attn_W, attn_b);
    k_soft_rho<<<1, 1024>>>(sentence, prev_probs, prev_word, x);
    k_ctx<<<256, 256>>>(enc);
    k_proj<<<128, 256>>>(comb_W, comb_b, Ws_W, Ws_b);
    k_gates<<<256, 256>>>(W_ih, W_hh, h0);
    k_cell<<<4, 256>>>(b_ih, b_hh, c0, out);
    k_scoreg<<<3142, 256>>>(Wo_W, Wo_b, out);
    dim3 g7(Sd / 128, Hd / 64);
    k_scorec<<<g7, 256>>>(enc, Wc_W, Wc_b, out);
    k_pmax<<<64, 256>>>(out);
    k_expsum<<<64, 256>>>(out);
    k_norm<<<64, 256>>>(out);
}